// round 9
// baseline (speedup 1.0000x reference)
#include <cuda_runtime.h>

// HMM forward: alpha_{t+1} = (alpha_t @ A) * Bo[t],  answer = sum(alpha_{T-1})
//
// R9 = R5's exact shape & math (128 CTAs x 256 thr, warp-per-float4-group,
// k-ascending FMA2 chains, xor butterfly == R1 tree; rel_err 9.477166e-4)
// with alpha consumed DIRECTLY from L2 via coalesced LDG.32 (one 128B line
// per warp per k) instead of staging into smem:
//   - deletes the per-step staging block + __syncthreads from the serial path
//   - removes 1024 alpha-LDS crossbar cycles/step (2656 -> 1760)
//   - frees 16KB smem: KS 51 -> 55, tier-3 33 -> 29 slots (-2MB/step L2)
// Visibility: tid0's __threadfence (gpu scope -> L1 IVALL) + bar.sync, the
// same chain all prior rounds used for the staging loads.

#define N_STATES 4096
#define SEQ_T    1024
#define N_OBS    128
#define NCTA     128
#define NTHR     256
#define COLS_PER_CTA 32

#define KR 44
#define KS 55
#define KT 29                       // 44+55+29 = 128
#define R_ROWS (KR * 32)            // 1408
#define S_ROWS (KS * 32)            // 1760
#define T3_OFF (R_ROWS + S_ROWS)    // 3168
#define T3_ROWS (KT * 32)           // 928
#define S_PITCH (S_ROWS + 1)        // 1761

// dynamic smem: sA[8][S_PITCH] float4 = 225,408 B (no s_alpha anymore)
#define SMEM_BYTES (8 * S_PITCH * 16)

typedef unsigned long long ull;

__device__ float    g_Bo[SEQ_T * N_STATES];
__device__ float4   g_A3T[1024 * T3_ROWS];     // [cg_global][row - T3_OFF]
__device__ float    g_alpha[2][N_STATES];
__device__ unsigned g_count;
__device__ unsigned g_sense;   // even #flips per launch -> restored

// ---------------------------------------------------------------------------
__global__ void gather_Bo_kernel(const float* __restrict__ B,
                                 const int*   __restrict__ obs_raw) {
    int any = 0;
    for (int k = 1 + 2 * (int)threadIdx.x; k < 1024; k += 2 * (int)blockDim.x)
        any |= obs_raw[k];
    int is32 = __syncthreads_or(any);

    int t = blockIdx.x;
    int o = is32 ? obs_raw[t] : obs_raw[2 * t];

    for (int j = threadIdx.x; j < N_STATES; j += blockDim.x)
        g_Bo[t * N_STATES + j] = B[j * N_OBS + o];
}

// ---------------------------------------------------------------------------
__global__ void transpose_A3_kernel(const float* __restrict__ A) {
    __shared__ float4 tile[32][33];
    const float4* A4 = reinterpret_cast<const float4*>(A);
    int r0 = blockIdx.x * 32;            // 29 tiles over 928 rows
    int c0 = blockIdx.y * 32;            // 32 tiles over 1024 col-groups
    int tx = threadIdx.x & 31, ty = threadIdx.x >> 5;
    #pragma unroll
    for (int p = 0; p < 4; ++p) {
        int r = r0 + ty + 8 * p;
        tile[ty + 8 * p][tx] = A4[(size_t)(T3_OFF + r) * 1024 + (c0 + tx)];
    }
    __syncthreads();
    #pragma unroll
    for (int p = 0; p < 4; ++p) {
        int c = c0 + ty + 8 * p;
        g_A3T[(size_t)c * T3_ROWS + (r0 + tx)] = tile[tx][ty + 8 * p];
    }
}

// ---------------------------------------------------------------------------
// Single-counter sense-reversing grid barrier (R5-proven; R7 showed fan-in
// is slower — same-address atomics pipeline at ~0.85 cyc in the LTS).
__device__ __forceinline__ void grid_barrier(unsigned& local_sense, unsigned nblocks) {
    __syncthreads();
    if (threadIdx.x == 0) {
        unsigned s = local_sense ^ 1u;
        local_sense = s;
        __threadfence();
        if (atomicAdd(&g_count, 1u) == nblocks - 1u) {
            g_count = 0u;
            __threadfence();
            atomicExch(&g_sense, s);
        } else {
            while (*(volatile unsigned*)&g_sense != s) { }
        }
        __threadfence();   // gpu-scope acquire: also invalidates L1 (CCTL.IVALL)
    }
    __syncthreads();
}

// packed f32x2 fma: component-wise IEEE fp32 fma (bit-identical to scalar)
__device__ __forceinline__ void fma2(ull& d, ull v, ull a) {
    asm("fma.rn.f32x2 %0, %1, %2, %0;" : "+l"(d) : "l"(v), "l"(a));
}
__device__ __forceinline__ ull pack2(float a) {
    ull r;
    asm("mov.b64 %0, {%1, %2};" : "=l"(r) : "f"(a), "f"(a));
    return r;
}

// ---------------------------------------------------------------------------
__global__ void __launch_bounds__(NTHR, 1)
hmm_forward_kernel(const float* __restrict__ A,
                   const float* __restrict__ pi,
                   float*       __restrict__ out) {
    extern __shared__ float smem[];
    float4* sA = reinterpret_cast<float4*>(smem);              // [8][S_PITCH]

    const int tid  = threadIdx.x;
    const int cta  = blockIdx.x;
    const int lane = tid & 31;            // row slot
    const int cg   = tid >> 5;            // warp id = column group, 0..7
    const int gcg  = cta * 8 + cg;
    const int col0 = cta * COLS_PER_CTA;

    const ulonglong2* __restrict__ A4u =
        reinterpret_cast<const ulonglong2*>(A);
    const float4* __restrict__ A4base =
        reinterpret_cast<const float4*>(A) + cta * 8;

    // ---- prologue: tier-1 rows in registers ----
    ulonglong2 rA[KR];
    #pragma unroll
    for (int k = 0; k < KR; ++k)
        rA[k] = A4u[(size_t)(lane + 32 * k) * 1024 + gcg];

    // ---- prologue: tier-2 rows into SMEM, [cg][row] layout ----
    for (int idx = tid; idx < S_ROWS * 8; idx += NTHR) {
        int cgf = idx & 7, rr = idx >> 3;
        sA[cgf * S_PITCH + rr] = A4base[(size_t)(R_ROWS + rr) * 1024 + cgf];
    }

    const ulonglong2* __restrict__ sAw =
        reinterpret_cast<const ulonglong2*>(sA + cg * S_PITCH);
    const ulonglong2* __restrict__ A3w =
        reinterpret_cast<const ulonglong2*>(g_A3T) + (size_t)gcg * T3_ROWS;

    unsigned local_sense = 0;

    // ---- alpha0 = pi * Bo[0] ----
    if (tid < COLS_PER_CTA) {
        int j = col0 + tid;
        g_alpha[0][j] = pi[j] * g_Bo[j];
    }
    grid_barrier(local_sense, gridDim.x);          // barrier #1

    int cur = 0;
    for (int t = 1; t < SEQ_T; ++t) {
        float4 bo;
        if (lane == 0)
            bo = reinterpret_cast<const float4*>(g_Bo + t * N_STATES)[gcg];

        // alpha read directly from L2 (coalesced 128B/line per warp per k)
        const float* __restrict__ ga = g_alpha[cur] + lane;

        // dot partials: i = lane + 32k, k ascending 0..127 (order contract)
        ull acc01 = 0ull, acc23 = 0ull;

        #pragma unroll
        for (int k = 0; k < KR; ++k) {                   // tier 1: registers
            ull aa = pack2(ga[32 * k]);
            fma2(acc01, rA[k].x, aa);
            fma2(acc23, rA[k].y, aa);
        }
        #pragma unroll 8
        for (int k = 0; k < KS; ++k) {                   // tier 2: SMEM
            ull aa = pack2(ga[R_ROWS + 32 * k]);
            ulonglong2 v = sAw[lane + 32 * k];
            fma2(acc01, v.x, aa);
            fma2(acc23, v.y, aa);
        }
        #pragma unroll 8
        for (int k = 0; k < KT; ++k) {                   // tier 3: L2 (transposed)
            ull aa = pack2(ga[T3_OFF + 32 * k]);
            ulonglong2 v = A3w[lane + 32 * k];
            fma2(acc01, v.x, aa);
            fma2(acc23, v.y, aa);
        }

        // unpack + xor butterfly (== R1's 32-slot tree at lane 0)
        float4 r;
        asm("mov.b64 {%0, %1}, %2;" : "=f"(r.x), "=f"(r.y) : "l"(acc01));
        asm("mov.b64 {%0, %1}, %2;" : "=f"(r.z), "=f"(r.w) : "l"(acc23));
        #pragma unroll
        for (int m = 16; m > 0; m >>= 1) {
            r.x += __shfl_xor_sync(0xffffffffu, r.x, m);
            r.y += __shfl_xor_sync(0xffffffffu, r.y, m);
            r.z += __shfl_xor_sync(0xffffffffu, r.z, m);
            r.w += __shfl_xor_sync(0xffffffffu, r.w, m);
        }

        if (lane == 0) {
            float4 o4;
            o4.x = r.x * bo.x; o4.y = r.y * bo.y;
            o4.z = r.z * bo.z; o4.w = r.w * bo.w;
            reinterpret_cast<float4*>(g_alpha[cur ^ 1])[gcg] = o4;
        }

        grid_barrier(local_sense, gridDim.x);      // barriers #2..#1024 (even)
        cur ^= 1;
    }

    // ---- final sum (CTA 0): R1's exact 256-thread tree (reuse smem) ----
    if (cta == 0) {
        float* sred = smem;            // sA no longer needed
        float s = 0.f;
        for (int i = tid; i < N_STATES; i += NTHR)
            s += g_alpha[cur][i];
        sred[tid] = s;
        __syncthreads();
        #pragma unroll
        for (int k = NTHR / 2; k > 0; k >>= 1) {
            if (tid < k) sred[tid] += sred[tid + k];
            __syncthreads();
        }
        if (tid == 0) out[0] = sred[0];
    }
}

// ---------------------------------------------------------------------------
extern "C" void kernel_launch(void* const* d_in, const int* in_sizes, int n_in,
                              void* d_out, int out_size) {
    const float* A   = (const float*)d_in[0];
    const float* B   = (const float*)d_in[1];
    const float* pi  = (const float*)d_in[2];
    const int*   obs = (const int*)d_in[3];
    float* out = (float*)d_out;

    cudaFuncSetAttribute(hmm_forward_kernel,
                         cudaFuncAttributeMaxDynamicSharedMemorySize, SMEM_BYTES);

    gather_Bo_kernel<<<SEQ_T, 256>>>(B, obs);
    dim3 tgrid(T3_ROWS / 32, 1024 / 32);
    transpose_A3_kernel<<<tgrid, 256>>>(A);
    hmm_forward_kernel<<<NCTA, NTHR, SMEM_BYTES>>>(A, pi, out);
}

// round 10
// speedup vs baseline: 1.2606x; 1.2606x over previous
#include <cuda_runtime.h>

// HMM forward: alpha_{t+1} = (alpha_t @ A) * Bo[t],  answer = sum(alpha_{T-1})
//
// R10 = R5 (best: 5388us; 128 CTA x 256 thr, warp-per-float4-group, staged
// alpha, k-ascending FMA2 chains, xor butterfly == R1 tree, single-counter
// barrier; rel_err 9.477166e-4) + software-pipelined tier-3:
//   - KR 44->40 frees 32 regs for an 8-deep LDG prefetch buffer (KT 33->37)
//   - pf[0..7] issued BEFORE the grid barrier (tier-3 A is static data;
//     bar.sync does not drain LDGs) -> latency hidden under barrier+tier1/2
//   - tier-3 loop consumes slot k, issues slot k+8 (rolling, fully unrolled)
// Consumption order identical -> bit-identical per-step alpha.

#define N_STATES 4096
#define SEQ_T    1024
#define N_OBS    128
#define NCTA     128
#define NTHR     256
#define COLS_PER_CTA 32

#define KR 40
#define KS 51
#define KT 37                       // 40+51+37 = 128
#define PFD 8                       // prefetch depth
#define R_ROWS (KR * 32)            // 1280
#define S_ROWS (KS * 32)            // 1632
#define T3_OFF (R_ROWS + S_ROWS)    // 2912
#define T3_ROWS (KT * 32)           // 1184
#define S_PITCH (S_ROWS + 1)        // 1633

// dynamic smem: sA[8][S_PITCH] float4 + s_alpha[4096] float = 225,408 B
#define SMEM_BYTES (8 * S_PITCH * 16 + N_STATES * 4)

typedef unsigned long long ull;

__device__ float    g_Bo[SEQ_T * N_STATES];
__device__ float4   g_A3T[1024 * T3_ROWS];     // [cg_global][row - T3_OFF]
__device__ float    g_alpha[2][N_STATES];
__device__ unsigned g_count;
__device__ unsigned g_sense;   // even #flips per launch -> restored

// ---------------------------------------------------------------------------
__global__ void gather_Bo_kernel(const float* __restrict__ B,
                                 const int*   __restrict__ obs_raw) {
    int any = 0;
    for (int k = 1 + 2 * (int)threadIdx.x; k < 1024; k += 2 * (int)blockDim.x)
        any |= obs_raw[k];
    int is32 = __syncthreads_or(any);

    int t = blockIdx.x;
    int o = is32 ? obs_raw[t] : obs_raw[2 * t];

    for (int j = threadIdx.x; j < N_STATES; j += blockDim.x)
        g_Bo[t * N_STATES + j] = B[j * N_OBS + o];
}

// ---------------------------------------------------------------------------
__global__ void transpose_A3_kernel(const float* __restrict__ A) {
    __shared__ float4 tile[32][33];
    const float4* A4 = reinterpret_cast<const float4*>(A);
    int r0 = blockIdx.x * 32;            // 37 tiles over 1184 rows
    int c0 = blockIdx.y * 32;            // 32 tiles over 1024 col-groups
    int tx = threadIdx.x & 31, ty = threadIdx.x >> 5;
    #pragma unroll
    for (int p = 0; p < 4; ++p) {
        int r = r0 + ty + 8 * p;
        tile[ty + 8 * p][tx] = A4[(size_t)(T3_OFF + r) * 1024 + (c0 + tx)];
    }
    __syncthreads();
    #pragma unroll
    for (int p = 0; p < 4; ++p) {
        int c = c0 + ty + 8 * p;
        g_A3T[(size_t)c * T3_ROWS + (r0 + tx)] = tile[tx][ty + 8 * p];
    }
}

// ---------------------------------------------------------------------------
// Single-counter sense-reversing grid barrier (R5-proven).
__device__ __forceinline__ void grid_barrier(unsigned& local_sense, unsigned nblocks) {
    __syncthreads();
    if (threadIdx.x == 0) {
        unsigned s = local_sense ^ 1u;
        local_sense = s;
        __threadfence();
        if (atomicAdd(&g_count, 1u) == nblocks - 1u) {
            g_count = 0u;
            __threadfence();
            atomicExch(&g_sense, s);
        } else {
            while (*(volatile unsigned*)&g_sense != s) { }
        }
        __threadfence();
    }
    __syncthreads();
}

// packed f32x2 fma: component-wise IEEE fp32 fma (bit-identical to scalar)
__device__ __forceinline__ void fma2(ull& d, ull v, ull a) {
    asm("fma.rn.f32x2 %0, %1, %2, %0;" : "+l"(d) : "l"(v), "l"(a));
}
__device__ __forceinline__ ull pack2(float a) {
    ull r;
    asm("mov.b64 %0, {%1, %2};" : "=l"(r) : "f"(a), "f"(a));
    return r;
}

// ---------------------------------------------------------------------------
__global__ void __launch_bounds__(NTHR, 1)
hmm_forward_kernel(const float* __restrict__ A,
                   const float* __restrict__ pi,
                   float*       __restrict__ out) {
    extern __shared__ float smem[];
    float4* sA      = reinterpret_cast<float4*>(smem);        // [8][S_PITCH]
    float*  s_alpha = smem + 8 * S_PITCH * 4;                 // 4096 floats

    const int tid  = threadIdx.x;
    const int cta  = blockIdx.x;
    const int lane = tid & 31;            // row slot
    const int cg   = tid >> 5;            // warp id = column group, 0..7
    const int gcg  = cta * 8 + cg;
    const int col0 = cta * COLS_PER_CTA;

    const ulonglong2* __restrict__ A4u =
        reinterpret_cast<const ulonglong2*>(A);
    const float4* __restrict__ A4base =
        reinterpret_cast<const float4*>(A) + cta * 8;

    // ---- prologue: tier-1 rows in registers ----
    ulonglong2 rA[KR];
    #pragma unroll
    for (int k = 0; k < KR; ++k)
        rA[k] = A4u[(size_t)(lane + 32 * k) * 1024 + gcg];

    // ---- prologue: tier-2 rows into SMEM, [cg][row] layout ----
    for (int idx = tid; idx < S_ROWS * 8; idx += NTHR) {
        int cgf = idx & 7, rr = idx >> 3;
        sA[cgf * S_PITCH + rr] = A4base[(size_t)(R_ROWS + rr) * 1024 + cgf];
    }

    const ulonglong2* __restrict__ sAw =
        reinterpret_cast<const ulonglong2*>(sA + cg * S_PITCH);
    const ulonglong2* __restrict__ A3w =
        reinterpret_cast<const ulonglong2*>(g_A3T) + (size_t)gcg * T3_ROWS;

    unsigned local_sense = 0;

    // ---- alpha0 = pi * Bo[0] ----
    if (tid < COLS_PER_CTA) {
        int j = col0 + tid;
        g_alpha[0][j] = pi[j] * g_Bo[j];
    }

    // ---- initial tier-3 prefetch (static data; overlaps barrier #1) ----
    ulonglong2 pf[PFD];
    #pragma unroll
    for (int j = 0; j < PFD; ++j)
        pf[j] = A3w[lane + 32 * j];

    grid_barrier(local_sense, gridDim.x);          // barrier #1

    int cur = 0;
    for (int t = 1; t < SEQ_T; ++t) {
        float4 bo;
        if (lane == 0)
            bo = reinterpret_cast<const float4*>(g_Bo + t * N_STATES)[gcg];

        // stage alpha into smem (1024 float4 = 4 per thread)
        {
            const float4* asrc = reinterpret_cast<const float4*>(g_alpha[cur]);
            float4*       adst = reinterpret_cast<float4*>(s_alpha);
            #pragma unroll
            for (int k = 0; k < 4; ++k)
                adst[tid + k * NTHR] = asrc[tid + k * NTHR];
        }
        __syncthreads();

        // dot partials: i = lane + 32k, k ascending 0..127 (order contract)
        ull acc01 = 0ull, acc23 = 0ull;

        #pragma unroll
        for (int k = 0; k < KR; ++k) {                   // tier 1: registers
            ull aa = pack2(s_alpha[lane + 32 * k]);
            fma2(acc01, rA[k].x, aa);
            fma2(acc23, rA[k].y, aa);
        }
        #pragma unroll 8
        for (int k = 0; k < KS; ++k) {                   // tier 2: SMEM
            ull aa = pack2(s_alpha[R_ROWS + lane + 32 * k]);
            ulonglong2 v = sAw[lane + 32 * k];
            fma2(acc01, v.x, aa);
            fma2(acc23, v.y, aa);
        }
        // tier 3: L2 via rolling 8-deep prefetch (consume k, issue k+PFD)
        #pragma unroll
        for (int k = 0; k < KT; ++k) {
            ull aa = pack2(s_alpha[T3_OFF + lane + 32 * k]);
            ulonglong2 v = pf[k & (PFD - 1)];
            if (k + PFD < KT)
                pf[k & (PFD - 1)] = A3w[lane + 32 * (k + PFD)];
            fma2(acc01, v.x, aa);
            fma2(acc23, v.y, aa);
        }

        // unpack + xor butterfly (== R1's 32-slot tree at lane 0)
        float4 r;
        asm("mov.b64 {%0, %1}, %2;" : "=f"(r.x), "=f"(r.y) : "l"(acc01));
        asm("mov.b64 {%0, %1}, %2;" : "=f"(r.z), "=f"(r.w) : "l"(acc23));
        #pragma unroll
        for (int m = 16; m > 0; m >>= 1) {
            r.x += __shfl_xor_sync(0xffffffffu, r.x, m);
            r.y += __shfl_xor_sync(0xffffffffu, r.y, m);
            r.z += __shfl_xor_sync(0xffffffffu, r.z, m);
            r.w += __shfl_xor_sync(0xffffffffu, r.w, m);
        }

        // re-issue next step's first PFD tier-3 slots (flies during barrier)
        #pragma unroll
        for (int j = 0; j < PFD; ++j)
            pf[j] = A3w[lane + 32 * j];

        if (lane == 0) {
            float4 o4;
            o4.x = r.x * bo.x; o4.y = r.y * bo.y;
            o4.z = r.z * bo.z; o4.w = r.w * bo.w;
            reinterpret_cast<float4*>(g_alpha[cur ^ 1])[gcg] = o4;
        }

        grid_barrier(local_sense, gridDim.x);      // barriers #2..#1024 (even)
        cur ^= 1;
    }

    // ---- final sum (CTA 0): R1's exact 256-thread tree ----
    if (cta == 0) {
        float s = 0.f;
        for (int i = tid; i < N_STATES; i += NTHR)
            s += g_alpha[cur][i];
        s_alpha[tid] = s;
        __syncthreads();
        #pragma unroll
        for (int k = NTHR / 2; k > 0; k >>= 1) {
            if (tid < k) s_alpha[tid] += s_alpha[tid + k];
            __syncthreads();
        }
        if (tid == 0) out[0] = s_alpha[0];
    }
}

// ---------------------------------------------------------------------------
extern "C" void kernel_launch(void* const* d_in, const int* in_sizes, int n_in,
                              void* d_out, int out_size) {
    const float* A   = (const float*)d_in[0];
    const float* B   = (const float*)d_in[1];
    const float* pi  = (const float*)d_in[2];
    const int*   obs = (const int*)d_in[3];
    float* out = (float*)d_out;

    cudaFuncSetAttribute(hmm_forward_kernel,
                         cudaFuncAttributeMaxDynamicSharedMemorySize, SMEM_BYTES);

    gather_Bo_kernel<<<SEQ_T, 256>>>(B, obs);
    dim3 tgrid(T3_ROWS / 32, 1024 / 32);
    transpose_A3_kernel<<<tgrid, 256>>>(A);
    hmm_forward_kernel<<<NCTA, NTHR, SMEM_BYTES>>>(A, pi, out);
}

// round 11
// speedup vs baseline: 1.3411x; 1.0638x over previous
#include <cuda_runtime.h>

// HMM forward: alpha_{t+1} = (alpha_t @ A) * Bo[t],  answer = sum(alpha_{T-1})
//
// R11 = R5's math (128 CTA x 256 thr, warp-per-float4-group, staged alpha,
// k-ascending FMA2 chains, xor butterfly == R1 tree; rel_err 9.477166e-4)
// with the three storage tiers INTERLEAVED in k instead of phase-sequential.
// Pattern (period 32, r = k%32):  r%3==0 -> RF (11/period, KR=44)
//                                 r%3==2 && r<=23 -> L2 (8/period, KT=32)
//                                 else -> SMEM (13/period, KS=52)
// Same chain order & values per (rs,col) -> bit-identical results. The mix
// spreads LSU work evenly, lets FMAs fill LDS/LDG shadows, and makes every
// address [base+imm] (no IMADs) in a fully-unrolled 128-slot loop.

#define N_STATES 4096
#define SEQ_T    1024
#define N_OBS    128
#define NCTA     128
#define NTHR     256
#define COLS_PER_CTA 32

#define KR 44                        // 4 periods x 11
#define KS 52                        // 4 periods x 13
#define KT 32                        // 4 periods x 8
#define S_ROWS (KS * 32)             // 1664 float4-rows per cg
#define S_PITCH (S_ROWS + 1)         // 1665
#define T3_ROWS (KT * 32)            // 1024

// dynamic smem: sA[8][S_PITCH] float4 (213,120B) + s_alpha[4096] f32 = 229,504B
#define SMEM_BYTES (8 * S_PITCH * 16 + N_STATES * 4)

typedef unsigned long long ull;

__device__ float    g_Bo[SEQ_T * N_STATES];
__device__ float4   g_A3T[1024 * T3_ROWS];     // [cg_global][slot*32 + lane]
__device__ float    g_alpha[2][N_STATES];
__device__ unsigned g_count;
__device__ unsigned g_sense;   // even #flips per launch -> restored

// ---------------------------------------------------------------------------
__global__ void gather_Bo_kernel(const float* __restrict__ B,
                                 const int*   __restrict__ obs_raw) {
    int any = 0;
    for (int k = 1 + 2 * (int)threadIdx.x; k < 1024; k += 2 * (int)blockDim.x)
        any |= obs_raw[k];
    int is32 = __syncthreads_or(any);

    int t = blockIdx.x;
    int o = is32 ? obs_raw[t] : obs_raw[2 * t];

    for (int j = threadIdx.x; j < N_STATES; j += blockDim.x)
        g_Bo[t * N_STATES + j] = B[j * N_OBS + o];
}

// ---------------------------------------------------------------------------
// Gather + transpose the KT L2-tier k-slots into g_A3T[cg][slot*32+lane].
// Slot s covers rows [32*k(s), 32*k(s)+32), k(s) = 32*(s/8) + (s%8)*3 + 2.
__global__ void transpose_A3_kernel(const float* __restrict__ A) {
    __shared__ float4 tile[32][33];
    const float4* A4 = reinterpret_cast<const float4*>(A);
    int s  = blockIdx.x;                 // 0..KT-1
    int kk = 32 * (s / 8) + (s % 8) * 3 + 2;
    int r0 = 32 * kk;
    int c0 = blockIdx.y * 32;
    int tx = threadIdx.x & 31, ty = threadIdx.x >> 5;
    #pragma unroll
    for (int p = 0; p < 4; ++p)
        tile[ty + 8 * p][tx] = A4[(size_t)(r0 + ty + 8 * p) * 1024 + (c0 + tx)];
    __syncthreads();
    #pragma unroll
    for (int p = 0; p < 4; ++p) {
        int c = c0 + ty + 8 * p;
        g_A3T[(size_t)c * T3_ROWS + s * 32 + tx] = tile[tx][ty + 8 * p];
    }
}

// ---------------------------------------------------------------------------
// Single-counter sense-reversing grid barrier (R5-proven).
__device__ __forceinline__ void grid_barrier(unsigned& local_sense, unsigned nblocks) {
    __syncthreads();
    if (threadIdx.x == 0) {
        unsigned s = local_sense ^ 1u;
        local_sense = s;
        __threadfence();
        if (atomicAdd(&g_count, 1u) == nblocks - 1u) {
            g_count = 0u;
            __threadfence();
            atomicExch(&g_sense, s);
        } else {
            while (*(volatile unsigned*)&g_sense != s) { }
        }
        __threadfence();
    }
    __syncthreads();
}

// packed f32x2 fma: component-wise IEEE fp32 fma (bit-identical to scalar)
__device__ __forceinline__ void fma2(ull& d, ull v, ull a) {
    asm("fma.rn.f32x2 %0, %1, %2, %0;" : "+l"(d) : "l"(v), "l"(a));
}
__device__ __forceinline__ ull pack2(float a) {
    ull r;
    asm("mov.b64 %0, {%1, %2};" : "=l"(r) : "f"(a), "f"(a));
    return r;
}

// ---------------------------------------------------------------------------
__global__ void __launch_bounds__(NTHR, 1)
hmm_forward_kernel(const float* __restrict__ A,
                   const float* __restrict__ pi,
                   float*       __restrict__ out) {
    extern __shared__ float smem[];
    float4* sA      = reinterpret_cast<float4*>(smem);        // [8][S_PITCH]
    float*  s_alpha = smem + 8 * S_PITCH * 4;                 // 4096 floats

    const int tid  = threadIdx.x;
    const int cta  = blockIdx.x;
    const int lane = tid & 31;            // row slot
    const int cg   = tid >> 5;            // warp id = column group, 0..7
    const int gcg  = cta * 8 + cg;
    const int col0 = cta * COLS_PER_CTA;

    const ulonglong2* __restrict__ A4u =
        reinterpret_cast<const ulonglong2*>(A);
    const float4* __restrict__ A4base =
        reinterpret_cast<const float4*>(A) + cta * 8;

    // ---- prologue: RF tier — k with (k%32)%3 == 0 (44 slots) ----
    ulonglong2 rA[KR];
    #pragma unroll
    for (int k = 0; k < 128; ++k) {
        int r = k & 31, p = k >> 5;
        if (r % 3 == 0)
            rA[p * 11 + r / 3] = A4u[(size_t)(lane + 32 * k) * 1024 + gcg];
    }

    // ---- prologue: SMEM tier (52 slots), sA[cg][slot*32 + row'] ----
    for (int idx = tid; idx < S_ROWS * 8; idx += NTHR) {
        int cgf = idx & 7;
        int rr  = idx >> 3;               // 0..S_ROWS-1
        int s = rr >> 5, rp = rr & 31;
        int m = s % 13, p = s / 13;
        int kk = 32 * p + ((m <= 10) ? 3 * m + 1 : (m == 11 ? 26 : 29));
        sA[cgf * S_PITCH + rr] = A4base[(size_t)(32 * kk + rp) * 1024 + cgf];
    }

    const ulonglong2* __restrict__ sAw =
        reinterpret_cast<const ulonglong2*>(sA + cg * S_PITCH);
    const ulonglong2* __restrict__ A3w =
        reinterpret_cast<const ulonglong2*>(g_A3T) + (size_t)gcg * T3_ROWS;

    unsigned local_sense = 0;

    // ---- alpha0 = pi * Bo[0] ----
    if (tid < COLS_PER_CTA) {
        int j = col0 + tid;
        g_alpha[0][j] = pi[j] * g_Bo[j];
    }
    grid_barrier(local_sense, gridDim.x);          // barrier #1

    int cur = 0;
    for (int t = 1; t < SEQ_T; ++t) {
        float4 bo;
        if (lane == 0)
            bo = reinterpret_cast<const float4*>(g_Bo + t * N_STATES)[gcg];

        // stage alpha into smem (1024 float4 = 4 per thread)
        {
            const float4* asrc = reinterpret_cast<const float4*>(g_alpha[cur]);
            float4*       adst = reinterpret_cast<float4*>(s_alpha);
            #pragma unroll
            for (int k = 0; k < 4; ++k)
                adst[tid + k * NTHR] = asrc[tid + k * NTHR];
        }
        __syncthreads();

        // dot partials: i = lane + 32k, k ascending 0..127 (order contract);
        // tier selection per k is compile-time -> fully mixed RF/LDS/LDG code.
        ull acc01 = 0ull, acc23 = 0ull;

        #pragma unroll
        for (int k = 0; k < 128; ++k) {
            int r = k & 31, p = k >> 5;
            ull aa = pack2(s_alpha[lane + 32 * k]);
            ulonglong2 v;
            if (r % 3 == 0)
                v = rA[p * 11 + r / 3];                          // RF
            else if (r % 3 == 2 && r <= 23)
                v = A3w[(p * 8 + r / 3) * 32 + lane];            // L2
            else
                v = sAw[(p * 13 + ((r % 3 == 1) ? r / 3
                                                : (r == 26 ? 11 : 12))) * 32
                        + lane];                                  // SMEM
            fma2(acc01, v.x, aa);
            fma2(acc23, v.y, aa);
        }

        // unpack + xor butterfly (== R1's 32-slot tree at lane 0)
        float4 r4;
        asm("mov.b64 {%0, %1}, %2;" : "=f"(r4.x), "=f"(r4.y) : "l"(acc01));
        asm("mov.b64 {%0, %1}, %2;" : "=f"(r4.z), "=f"(r4.w) : "l"(acc23));
        #pragma unroll
        for (int m = 16; m > 0; m >>= 1) {
            r4.x += __shfl_xor_sync(0xffffffffu, r4.x, m);
            r4.y += __shfl_xor_sync(0xffffffffu, r4.y, m);
            r4.z += __shfl_xor_sync(0xffffffffu, r4.z, m);
            r4.w += __shfl_xor_sync(0xffffffffu, r4.w, m);
        }

        if (lane == 0) {
            float4 o4;
            o4.x = r4.x * bo.x; o4.y = r4.y * bo.y;
            o4.z = r4.z * bo.z; o4.w = r4.w * bo.w;
            reinterpret_cast<float4*>(g_alpha[cur ^ 1])[gcg] = o4;
        }

        grid_barrier(local_sense, gridDim.x);      // barriers #2..#1024 (even)
        cur ^= 1;
    }

    // ---- final sum (CTA 0): R1's exact 256-thread tree ----
    if (cta == 0) {
        float s = 0.f;
        for (int i = tid; i < N_STATES; i += NTHR)
            s += g_alpha[cur][i];
        s_alpha[tid] = s;
        __syncthreads();
        #pragma unroll
        for (int k = NTHR / 2; k > 0; k >>= 1) {
            if (tid < k) s_alpha[tid] += s_alpha[tid + k];
            __syncthreads();
        }
        if (tid == 0) out[0] = s_alpha[0];
    }
}

// ---------------------------------------------------------------------------
extern "C" void kernel_launch(void* const* d_in, const int* in_sizes, int n_in,
                              void* d_out, int out_size) {
    const float* A   = (const float*)d_in[0];
    const float* B   = (const float*)d_in[1];
    const float* pi  = (const float*)d_in[2];
    const int*   obs = (const int*)d_in[3];
    float* out = (float*)d_out;

    cudaFuncSetAttribute(hmm_forward_kernel,
                         cudaFuncAttributeMaxDynamicSharedMemorySize, SMEM_BYTES);

    gather_Bo_kernel<<<SEQ_T, 256>>>(B, obs);
    dim3 tgrid(KT, 1024 / 32);
    transpose_A3_kernel<<<tgrid, 256>>>(A);
    hmm_forward_kernel<<<NCTA, NTHR, SMEM_BYTES>>>(A, pi, out);
}

// round 12
// speedup vs baseline: 1.3894x; 1.0360x over previous
#include <cuda_runtime.h>

// HMM forward: alpha_{t+1} = (alpha_t @ A) * Bo[t],  answer = sum(alpha_{T-1})
//
// R12 = R11 (tier-interleaved k-slots, bit-identical math to R1; 5069us)
//  + single fused kernel (gather_Bo + A3T transpose folded into the forward
//    kernel's prologue, before grid barrier #1) -> ncu finally samples the
//    kernel that matters, and 2 graph launches disappear.
//  + cross-period prefetch ring for the L2 tier: g_A3T is static data, so an
//    8-slot register ring loads period p+1's values during period p (wrapping
//    to period 0 of the NEXT step at p=3). ~250+ cyc lead per LDG.
// Tier pattern per k (r = k%32): r%3==0 -> RF(44) ; r%3==2 && r<=23 -> L2(32)
// via ring ; else SMEM(52). Chain order k=0..127 and values unchanged ->
// per-step alpha bit-identical (rel_err 9.477166e-4).

#define N_STATES 4096
#define SEQ_T    1024
#define N_OBS    128
#define NCTA     128
#define NTHR     256
#define COLS_PER_CTA 32

#define KR 44                        // 4 periods x 11
#define KS 52                        // 4 periods x 13
#define KT 32                        // 4 periods x 8
#define S_ROWS (KS * 32)             // 1664
#define S_PITCH (S_ROWS + 1)         // 1665
#define T3_ROWS (KT * 32)            // 1024

// dynamic smem: sA[8][S_PITCH] float4 (213,120B) + s_alpha[4096] f32 = 229,504B
#define SMEM_BYTES (8 * S_PITCH * 16 + N_STATES * 4)

typedef unsigned long long ull;

__device__ float    g_Bo[SEQ_T * N_STATES];
__device__ float4   g_A3T[1024 * T3_ROWS];     // [cg_global][slot*32 + lane]
__device__ float    g_alpha[2][N_STATES];
__device__ unsigned g_count;
__device__ unsigned g_sense;   // even #flips per launch -> restored

// ---------------------------------------------------------------------------
// Single-counter sense-reversing grid barrier (R5-proven; fan-in was slower).
__device__ __forceinline__ void grid_barrier(unsigned& local_sense, unsigned nblocks) {
    __syncthreads();
    if (threadIdx.x == 0) {
        unsigned s = local_sense ^ 1u;
        local_sense = s;
        __threadfence();
        if (atomicAdd(&g_count, 1u) == nblocks - 1u) {
            g_count = 0u;
            __threadfence();
            atomicExch(&g_sense, s);
        } else {
            while (*(volatile unsigned*)&g_sense != s) { }
        }
        __threadfence();
    }
    __syncthreads();
}

// packed f32x2 fma: component-wise IEEE fp32 fma (bit-identical to scalar)
__device__ __forceinline__ void fma2(ull& d, ull v, ull a) {
    asm("fma.rn.f32x2 %0, %1, %2, %0;" : "+l"(d) : "l"(v), "l"(a));
}
__device__ __forceinline__ ull pack2(float a) {
    ull r;
    asm("mov.b64 %0, {%1, %2};" : "=l"(r) : "f"(a), "f"(a));
    return r;
}

// ---------------------------------------------------------------------------
__global__ void __launch_bounds__(NTHR, 1)
hmm_forward_kernel(const float* __restrict__ A,
                   const float* __restrict__ B,
                   const int*   __restrict__ obs_raw,
                   const float* __restrict__ pi,
                   float*       __restrict__ out) {
    extern __shared__ float smem[];
    float4* sA      = reinterpret_cast<float4*>(smem);        // [8][S_PITCH]
    float*  s_alpha = smem + 8 * S_PITCH * 4;                 // 4096 floats

    const int tid  = threadIdx.x;
    const int cta  = blockIdx.x;
    const int lane = tid & 31;            // row slot
    const int cg   = tid >> 5;            // warp id = column group, 0..7
    const int gcg  = cta * 8 + cg;
    const int col0 = cta * COLS_PER_CTA;

    const float4*     __restrict__ A4 = reinterpret_cast<const float4*>(A);
    const ulonglong2* __restrict__ A4u = reinterpret_cast<const ulonglong2*>(A);
    const float4*     __restrict__ A4base = A4 + cta * 8;

    // ================= PROLOGUE (all before grid barrier #1) =================

    // -- obs element-width detect (int64 little-endian: odd dwords are 0) --
    int any = 0;
    for (int k = 1 + 2 * tid; k < 1024; k += 2 * NTHR)
        any |= obs_raw[k];
    int is32 = __syncthreads_or(any);

    // -- A3T transpose: 1024 (slot, col-block) tile tasks over 128 CTAs --
    {
        float4 (*tile)[33] = reinterpret_cast<float4(*)[33]>(smem); // scratch
        int tx = tid & 31, ty = tid >> 5;              // ty 0..7
        for (int task = cta; task < KT * 32; task += NCTA) {
            int s  = task & 31;                        // slot 0..31
            int cb = task >> 5;                        // col block 0..31
            int kk = 32 * (s / 8) + (s % 8) * 3 + 2;   // interleave pattern
            int r0 = 32 * kk, c0 = cb * 32;
            #pragma unroll
            for (int p = 0; p < 4; ++p)
                tile[ty + 8 * p][tx] =
                    A4[(size_t)(r0 + ty + 8 * p) * 1024 + (c0 + tx)];
            __syncthreads();
            #pragma unroll
            for (int p = 0; p < 4; ++p)
                g_A3T[(size_t)(c0 + ty + 8 * p) * T3_ROWS + s * 32 + tx] =
                    tile[tx][ty + 8 * p];
            __syncthreads();
        }
    }

    // -- Bo gather: 8 timesteps per CTA --
    for (int t = cta; t < SEQ_T; t += NCTA) {
        int o = is32 ? obs_raw[t] : obs_raw[2 * t];
        for (int j = tid; j < N_STATES; j += NTHR)
            g_Bo[t * N_STATES + j] = B[j * N_OBS + o];
    }

    // -- RF tier: k with (k%32)%3 == 0 (44 slots) --
    ulonglong2 rA[KR];
    #pragma unroll
    for (int k = 0; k < 128; ++k) {
        int r = k & 31, p = k >> 5;
        if (r % 3 == 0)
            rA[p * 11 + r / 3] = A4u[(size_t)(lane + 32 * k) * 1024 + gcg];
    }

    // -- SMEM tier (52 slots), sA[cg][slot*32 + row'] (after scratch done) --
    for (int idx = tid; idx < S_ROWS * 8; idx += NTHR) {
        int cgf = idx & 7;
        int rr  = idx >> 3;
        int s = rr >> 5, rp = rr & 31;
        int m = s % 13, p = s / 13;
        int kk = 32 * p + ((m <= 10) ? 3 * m + 1 : (m == 11 ? 26 : 29));
        sA[cgf * S_PITCH + rr] = A4base[(size_t)(32 * kk + rp) * 1024 + cgf];
    }

    const ulonglong2* __restrict__ sAw =
        reinterpret_cast<const ulonglong2*>(sA + cg * S_PITCH);
    const ulonglong2* __restrict__ A3w =
        reinterpret_cast<const ulonglong2*>(g_A3T) + (size_t)gcg * T3_ROWS;

    // -- alpha0 = pi * Bo[0] (this CTA gathered t=0 iff cta==0; but all Bo
    //    writes complete only after barrier #1, so read pi*B directly) --
    if (tid < COLS_PER_CTA) {
        int j = col0 + tid;
        int o0 = is32 ? obs_raw[0] : 0;
        if (!is32) o0 = obs_raw[0];
        g_alpha[0][j] = pi[j] * B[j * N_OBS + o0];
    }

    unsigned local_sense = 0;
    grid_barrier(local_sense, gridDim.x);          // barrier #1

    // -- prefetch ring: period 0's L2 slots (static data, reused each step) --
    ulonglong2 pf[8];
    #pragma unroll
    for (int s = 0; s < 8; ++s)
        pf[s] = A3w[s * 32 + lane];

    // ========================== MAIN SCAN LOOP ==========================
    int cur = 0;
    for (int t = 1; t < SEQ_T; ++t) {
        float4 bo;
        if (lane == 0)
            bo = reinterpret_cast<const float4*>(g_Bo + t * N_STATES)[gcg];

        // stage alpha into smem (1024 float4 = 4 per thread)
        {
            const float4* asrc = reinterpret_cast<const float4*>(g_alpha[cur]);
            float4*       adst = reinterpret_cast<float4*>(s_alpha);
            #pragma unroll
            for (int k = 0; k < 4; ++k)
                adst[tid + k * NTHR] = asrc[tid + k * NTHR];
        }
        __syncthreads();

        // dot partials: i = lane + 32k, k ascending 0..127 (order contract)
        ull acc01 = 0ull, acc23 = 0ull;

        #pragma unroll
        for (int k = 0; k < 128; ++k) {
            int r = k & 31, p = k >> 5;
            ull aa = pack2(s_alpha[lane + 32 * k]);
            ulonglong2 v;
            if (r % 3 == 0) {
                v = rA[p * 11 + r / 3];                          // RF
            } else if (r % 3 == 2 && r <= 23) {
                int s = r / 3;                                   // 0..7
                v = pf[s];                                       // L2 (ring)
                int np = (p + 1) & 3;                            // next period
                pf[s] = A3w[(np * 8 + s) * 32 + lane];           // refill
            } else {
                v = sAw[(p * 13 + ((r % 3 == 1) ? r / 3
                                                : (r == 26 ? 11 : 12))) * 32
                        + lane];                                  // SMEM
            }
            fma2(acc01, v.x, aa);
            fma2(acc23, v.y, aa);
        }

        // unpack + xor butterfly (== R1's 32-slot tree at lane 0)
        float4 r4;
        asm("mov.b64 {%0, %1}, %2;" : "=f"(r4.x), "=f"(r4.y) : "l"(acc01));
        asm("mov.b64 {%0, %1}, %2;" : "=f"(r4.z), "=f"(r4.w) : "l"(acc23));
        #pragma unroll
        for (int m = 16; m > 0; m >>= 1) {
            r4.x += __shfl_xor_sync(0xffffffffu, r4.x, m);
            r4.y += __shfl_xor_sync(0xffffffffu, r4.y, m);
            r4.z += __shfl_xor_sync(0xffffffffu, r4.z, m);
            r4.w += __shfl_xor_sync(0xffffffffu, r4.w, m);
        }

        if (lane == 0) {
            float4 o4;
            o4.x = r4.x * bo.x; o4.y = r4.y * bo.y;
            o4.z = r4.z * bo.z; o4.w = r4.w * bo.w;
            reinterpret_cast<float4*>(g_alpha[cur ^ 1])[gcg] = o4;
        }

        grid_barrier(local_sense, gridDim.x);      // barriers #2..#1024 (even)
        cur ^= 1;
    }

    // ---- final sum (CTA 0): R1's exact 256-thread tree ----
    if (cta == 0) {
        float s = 0.f;
        for (int i = tid; i < N_STATES; i += NTHR)
            s += g_alpha[cur][i];
        s_alpha[tid] = s;
        __syncthreads();
        #pragma unroll
        for (int k = NTHR / 2; k > 0; k >>= 1) {
            if (tid < k) s_alpha[tid] += s_alpha[tid + k];
            __syncthreads();
        }
        if (tid == 0) out[0] = s_alpha[0];
    }
}

// ---------------------------------------------------------------------------
extern "C" void kernel_launch(void* const* d_in, const int* in_sizes, int n_in,
                              void* d_out, int out_size) {
    const float* A   = (const float*)d_in[0];
    const float* B   = (const float*)d_in[1];
    const float* pi  = (const float*)d_in[2];
    const int*   obs = (const int*)d_in[3];
    float* out = (float*)d_out;

    cudaFuncSetAttribute(hmm_forward_kernel,
                         cudaFuncAttributeMaxDynamicSharedMemorySize, SMEM_BYTES);

    hmm_forward_kernel<<<NCTA, NTHR, SMEM_BYTES>>>(A, B, obs, pi, out);
}